// round 2
// baseline (speedup 1.0000x reference)
#include <cuda_runtime.h>
#include <math.h>

#define N_NODES 100000
#define N_EDGES 800000
#define C 128

// ---------------- scratch (static device globals; no allocation) -------------
__device__ float g_q[(size_t)N_NODES * C];
__device__ float g_k[(size_t)N_NODES * C];
__device__ float g_v[(size_t)N_NODES * C];
__device__ float g_h[(size_t)N_NODES * C];   // layer-1 output / layer-2 input
__device__ float g_sc[N_EDGES];              // score, then exp(score - max) in place
__device__ float g_max[N_NODES];
__device__ float g_sum[N_NODES];
__device__ int   g_src[N_EDGES];
__device__ int   g_dst[N_EDGES];
__device__ int   g_is64;                     // 1 if edge_index is int64, else int32

// ---------------- packed f32x2 helpers (Blackwell) ---------------------------
typedef unsigned long long ull;

__device__ __forceinline__ ull pack2(float lo, float hi) {
    ull r;
    asm("mov.b64 %0, {%1, %2};" : "=l"(r) : "f"(lo), "f"(hi));
    return r;
}
__device__ __forceinline__ ull fma2(ull a, ull b, ull c) {
    ull d;
    asm("fma.rn.f32x2 %0, %1, %2, %3;" : "=l"(d) : "l"(a), "l"(b), "l"(c));
    return d;
}
__device__ __forceinline__ void unpack2(ull v, float& lo, float& hi) {
    asm("mov.b64 {%0, %1}, %2;" : "=f"(lo), "=f"(hi) : "l"(v));
}

// ---------------- edge-index dtype probe + convert ---------------------------
__global__ void detect_idx_dtype(const void* __restrict__ ei_raw) {
    // Deterministic: interpret first 64 words as int64; if ALL are valid node
    // ids the buffer is int64 (an int32 buffer packs two random ids per word,
    // giving values >= 2^32 unless the high id is 0 -> P(all 64 pass) ~ 1e-320).
    const long long* p = (const long long*)ei_raw;
    int ok = 1;
    for (int i = 0; i < 64; i++) {
        long long v = p[i];
        if (v < 0 || v >= N_NODES) { ok = 0; break; }
    }
    g_is64 = ok;
}

__global__ void convert_idx(const void* __restrict__ ei_raw) {
    int i = blockIdx.x * blockDim.x + threadIdx.x;
    if (i >= 2 * N_EDGES) return;
    int v;
    if (g_is64) v = (int)((const long long*)ei_raw)[i];
    else        v = ((const int*)ei_raw)[i];
    if (i < N_EDGES) g_src[i] = v;
    else             g_dst[i - N_EDGES] = v;
}

// ---------------- init segment buffers ---------------------------------------
__global__ void init_seg() {
    int i = blockIdx.x * blockDim.x + threadIdx.x;
    if (i < N_NODES) {
        g_max[i] = -INFINITY;
        g_sum[i] = 0.0f;
    }
}

// ---------------- fused 4-way GEMM: X[N,128] @ W[128,128] + b ----------------
// grid = (ceil(N/128), 4); y selects (Wq->g_q, Wk->g_k, Wv->g_v, Ws->skip_out)
// X == nullptr means "read g_h"; skip_out == nullptr means "write g_h".
template <bool RELU>
__global__ void __launch_bounds__(256) gemm4(
    const float* __restrict__ Xin,
    const float* __restrict__ Wq, const float* __restrict__ bq,
    const float* __restrict__ Wk, const float* __restrict__ bk,
    const float* __restrict__ Wv, const float* __restrict__ bv,
    const float* __restrict__ Ws, const float* __restrict__ bs,
    float* __restrict__ skip_out)
{
    const float* X = Xin ? Xin : g_h;
    const float* W;
    const float* bias;
    float* Cout;
    switch (blockIdx.y) {
        case 0:  W = Wq; bias = bq; Cout = g_q; break;
        case 1:  W = Wk; bias = bk; Cout = g_k; break;
        case 2:  W = Wv; bias = bv; Cout = g_v; break;
        default: W = Ws; bias = bs; Cout = skip_out ? skip_out : g_h; break;
    }

    __shared__ float Xs[32][132];   // [k][m], padded (row stride 528B, 16B-mult)
    __shared__ float Wsm[32][128];  // [k][n]

    const int tid = threadIdx.x;
    const int tx = tid & 15;        // output-col group
    const int ty = tid >> 4;        // output-row group
    const int m0 = blockIdx.x * 128;

    ull acc[8][4];                  // rows i=0..7, packed col pairs jj=0..3
#pragma unroll
    for (int i = 0; i < 8; i++)
#pragma unroll
        for (int jj = 0; jj < 4; jj++) acc[i][jj] = 0ULL;

    for (int k0 = 0; k0 < 128; k0 += 32) {
        // load X tile (128 rows x 32 k), store transposed into Xs[k][m]
#pragma unroll
        for (int it = 0; it < 4; it++) {
            int idx = it * 256 + tid;    // 0..1023 float4 slots
            int row = idx >> 3;          // 0..127
            int f4  = idx & 7;           // 0..7
            int gr = m0 + row;
            float4 xv = make_float4(0.f, 0.f, 0.f, 0.f);
            if (gr < N_NODES) {
                xv = *reinterpret_cast<const float4*>(X + (size_t)gr * C + k0 + f4 * 4);
                if (RELU) {
                    xv.x = fmaxf(xv.x, 0.f); xv.y = fmaxf(xv.y, 0.f);
                    xv.z = fmaxf(xv.z, 0.f); xv.w = fmaxf(xv.w, 0.f);
                }
            }
            Xs[f4 * 4 + 0][row] = xv.x;
            Xs[f4 * 4 + 1][row] = xv.y;
            Xs[f4 * 4 + 2][row] = xv.z;
            Xs[f4 * 4 + 3][row] = xv.w;
        }
        // load W tile (32 k x 128 n)
#pragma unroll
        for (int it = 0; it < 4; it++) {
            int idx = it * 256 + tid;
            int kk = idx >> 5;           // 0..31
            int f4 = idx & 31;           // 0..31
            float4 wv = *reinterpret_cast<const float4*>(W + (size_t)(k0 + kk) * C + f4 * 4);
            *reinterpret_cast<float4*>(&Wsm[kk][f4 * 4]) = wv;
        }
        __syncthreads();

#pragma unroll
        for (int kk = 0; kk < 32; kk++) {
            float4 a0 = *reinterpret_cast<float4*>(&Xs[kk][ty * 8]);
            float4 a1 = *reinterpret_cast<float4*>(&Xs[kk][ty * 8 + 4]);
            // w pairs straight from smem as 64-bit lanes (no pack needed)
            ulonglong2 wA = *reinterpret_cast<ulonglong2*>(&Wsm[kk][tx * 8]);
            ull wp0 = wA.x, wp1 = wA.y;
            ulonglong2 wB = *reinterpret_cast<ulonglong2*>(&Wsm[kk][tx * 8 + 4]);
            ull wp2 = wB.x, wp3 = wB.y;
            float am[8] = {a0.x, a0.y, a0.z, a0.w, a1.x, a1.y, a1.z, a1.w};
#pragma unroll
            for (int i = 0; i < 8; i++) {
                ull ad = pack2(am[i], am[i]);
                acc[i][0] = fma2(ad, wp0, acc[i][0]);
                acc[i][1] = fma2(ad, wp1, acc[i][1]);
                acc[i][2] = fma2(ad, wp2, acc[i][2]);
                acc[i][3] = fma2(ad, wp3, acc[i][3]);
            }
        }
        __syncthreads();
    }

    // epilogue: add bias, store
    const int col = tx * 8;
    float bb[8];
#pragma unroll
    for (int j = 0; j < 8; j++) bb[j] = __ldg(bias + col + j);

#pragma unroll
    for (int i = 0; i < 8; i++) {
        int gr = m0 + ty * 8 + i;
        if (gr < N_NODES) {
            float o[8];
#pragma unroll
            for (int jj = 0; jj < 4; jj++) unpack2(acc[i][jj], o[2 * jj], o[2 * jj + 1]);
            float4 s0 = make_float4(o[0] + bb[0], o[1] + bb[1], o[2] + bb[2], o[3] + bb[3]);
            float4 s1 = make_float4(o[4] + bb[4], o[5] + bb[5], o[6] + bb[6], o[7] + bb[7]);
            *reinterpret_cast<float4*>(Cout + (size_t)gr * C + col)     = s0;
            *reinterpret_cast<float4*>(Cout + (size_t)gr * C + col + 4) = s1;
        }
    }
}

// ---------------- edge kernels -----------------------------------------------
__global__ void __launch_bounds__(256) edge_score() {
    int warp = (blockIdx.x * 256 + threadIdx.x) >> 5;
    int lane = threadIdx.x & 31;
    if (warp >= N_EDGES) return;
    int src = g_src[warp];
    int dst = g_dst[warp];
    float4 q4 = *reinterpret_cast<const float4*>(g_q + (size_t)dst * C + lane * 4);
    float4 k4 = *reinterpret_cast<const float4*>(g_k + (size_t)src * C + lane * 4);
    float s = q4.x * k4.x + q4.y * k4.y + q4.z * k4.z + q4.w * k4.w;
#pragma unroll
    for (int o = 16; o; o >>= 1) s += __shfl_xor_sync(0xffffffffu, s, o);
    s *= 0.0883883476483184405f;   // 1/sqrt(128)
    if (lane == 0) {
        g_sc[warp] = s;
        // float atomic max via ordered int/uint views (g_max init = -inf)
        if (s >= 0.f) atomicMax((int*)&g_max[dst], __float_as_int(s));
        else          atomicMin((unsigned int*)&g_max[dst], __float_as_uint(s));
    }
}

__global__ void __launch_bounds__(256) edge_exp() {
    int e = blockIdx.x * 256 + threadIdx.x;
    if (e >= N_EDGES) return;
    int dst = g_dst[e];
    float w = __expf(g_sc[e] - g_max[dst]);
    g_sc[e] = w;
    atomicAdd(&g_sum[dst], w);
}

__global__ void __launch_bounds__(256) edge_scatter(float* __restrict__ outp) {
    float* out = outp ? outp : g_h;
    int warp = (blockIdx.x * 256 + threadIdx.x) >> 5;
    int lane = threadIdx.x & 31;
    if (warp >= N_EDGES) return;
    int src = g_src[warp];
    int dst = g_dst[warp];
    float alpha = g_sc[warp] / g_sum[dst];
    float4 v4 = *reinterpret_cast<const float4*>(g_v + (size_t)src * C + lane * 4);
    float* p = out + (size_t)dst * C + lane * 4;
    atomicAdd(p + 0, alpha * v4.x);
    atomicAdd(p + 1, alpha * v4.y);
    atomicAdd(p + 2, alpha * v4.z);
    atomicAdd(p + 3, alpha * v4.w);
}

// ---------------- launch ------------------------------------------------------
extern "C" void kernel_launch(void* const* d_in, const int* in_sizes, int n_in,
                              void* d_out, int out_size) {
    const float* x  = (const float*)d_in[0];
    const void*  ei = d_in[1];
    const float *Wq1 = (const float*)d_in[2],  *bq1 = (const float*)d_in[3];
    const float *Wk1 = (const float*)d_in[4],  *bk1 = (const float*)d_in[5];
    const float *Wv1 = (const float*)d_in[6],  *bv1 = (const float*)d_in[7];
    const float *Ws1 = (const float*)d_in[8],  *bs1 = (const float*)d_in[9];
    const float *Wq2 = (const float*)d_in[10], *bq2 = (const float*)d_in[11];
    const float *Wk2 = (const float*)d_in[12], *bk2 = (const float*)d_in[13];
    const float *Wv2 = (const float*)d_in[14], *bv2 = (const float*)d_in[15];
    const float *Ws2 = (const float*)d_in[16], *bs2 = (const float*)d_in[17];
    float* out = (float*)d_out;

    const dim3 ggrid((N_NODES + 127) / 128, 4);
    const int  nblk   = (N_NODES + 255) / 256;
    const int  cblk   = (2 * N_EDGES + 255) / 256;
    const int  eblk_w = (N_EDGES * 32 + 255) / 256;   // warp-per-edge kernels
    const int  eblk_t = (N_EDGES + 255) / 256;        // thread-per-edge kernels

    // -------- prep: edge-index dtype probe + int32 conversion --------
    detect_idx_dtype<<<1, 1>>>(ei);
    convert_idx<<<cblk, 256>>>(ei);

    // -------- layer 1 --------
    init_seg<<<nblk, 256>>>();
    gemm4<false><<<ggrid, 256>>>(x, Wq1, bq1, Wk1, bk1, Wv1, bv1, Ws1, bs1, nullptr);
    edge_score<<<eblk_w, 256>>>();
    edge_exp<<<eblk_t, 256>>>();
    edge_scatter<<<eblk_w, 256>>>(nullptr);           // into g_h (holds skip)

    // -------- layer 2 (relu fused into GEMM load) --------
    init_seg<<<nblk, 256>>>();
    gemm4<true><<<ggrid, 256>>>(nullptr, Wq2, bq2, Wk2, bk2, Wv2, bv2, Ws2, bs2, out);
    edge_score<<<eblk_w, 256>>>();
    edge_exp<<<eblk_t, 256>>>();
    edge_scatter<<<eblk_w, 256>>>(out);               // into d_out (holds skip)
}

// round 3
// speedup vs baseline: 1.4276x; 1.4276x over previous
#include <cuda_runtime.h>
#include <math.h>

#define N_NODES 100000
#define N_EDGES 800000
#define C 128
#define SCAP 128   // per-warp smem score capacity (max degree fast path)

// ---------------- scratch (static device globals; no allocation) -------------
__device__ float g_q[(size_t)N_NODES * C];
__device__ float g_k[(size_t)N_NODES * C];
__device__ float g_v[(size_t)N_NODES * C];
__device__ float g_h[(size_t)N_NODES * C];   // layer-1 output / layer-2 input
__device__ float g_sc[N_EDGES];              // overflow score buffer (deg > SCAP)
__device__ int   g_src[N_EDGES];
__device__ int   g_dst[N_EDGES];
__device__ int   g_deg[N_NODES];
__device__ int   g_cur[N_NODES];
__device__ int   g_rowptr[N_NODES + 1];
__device__ int   g_csrc[N_EDGES];            // src ids in CSR (dst-grouped) order
__device__ int   g_is64;

// ---------------- packed f32x2 helpers (Blackwell) ---------------------------
typedef unsigned long long ull;

__device__ __forceinline__ ull pack2(float lo, float hi) {
    ull r;
    asm("mov.b64 %0, {%1, %2};" : "=l"(r) : "f"(lo), "f"(hi));
    return r;
}
__device__ __forceinline__ ull fma2(ull a, ull b, ull c) {
    ull d;
    asm("fma.rn.f32x2 %0, %1, %2, %3;" : "=l"(d) : "l"(a), "l"(b), "l"(c));
    return d;
}
__device__ __forceinline__ void unpack2(ull v, float& lo, float& hi) {
    asm("mov.b64 {%0, %1}, %2;" : "=f"(lo), "=f"(hi) : "l"(v));
}

// ---------------- CSR build ---------------------------------------------------
__global__ void detect_idx_dtype(const void* __restrict__ ei_raw) {
    // Deterministic: int32 buffer read as int64 packs two random node ids per
    // word -> value >= 2^32 almost surely; 64 consecutive passes => int64.
    const long long* p = (const long long*)ei_raw;
    int ok = 1;
    for (int i = 0; i < 64; i++) {
        long long v = p[i];
        if (v < 0 || v >= N_NODES) { ok = 0; break; }
    }
    g_is64 = ok;
}

__global__ void zero_counts() {
    int i = blockIdx.x * blockDim.x + threadIdx.x;
    if (i < N_NODES) { g_deg[i] = 0; g_cur[i] = 0; }
}

__global__ void convert_hist(const void* __restrict__ ei_raw) {
    int i = blockIdx.x * blockDim.x + threadIdx.x;
    if (i >= 2 * N_EDGES) return;
    int v;
    if (g_is64) v = (int)((const long long*)ei_raw)[i];
    else        v = ((const int*)ei_raw)[i];
    if (i < N_EDGES) g_src[i] = v;
    else { g_dst[i - N_EDGES] = v; atomicAdd(&g_deg[v], 1); }
}

// single-block exclusive scan of g_deg -> g_rowptr (1024 threads x 98 chunk)
__global__ void __launch_bounds__(1024) scan_deg() {
    const int CH = 98;                       // 1024*98 = 100352 >= N_NODES
    __shared__ float dummy;
    __shared__ int ssum[1024];
    int tid = threadIdx.x;
    int base = tid * CH;
    int s = 0;
    for (int j = 0; j < CH; j++) {
        int idx = base + j;
        if (idx < N_NODES) s += g_deg[idx];
    }
    ssum[tid] = s;
    __syncthreads();
    // inclusive Hillis-Steele scan
    for (int off = 1; off < 1024; off <<= 1) {
        int add = (tid >= off) ? ssum[tid - off] : 0;
        __syncthreads();
        ssum[tid] += add;
        __syncthreads();
    }
    int offp = ssum[tid] - s;                // exclusive prefix for this thread
    for (int j = 0; j < CH; j++) {
        int idx = base + j;
        if (idx < N_NODES) {
            g_rowptr[idx] = offp;
            offp += g_deg[idx];
            if (idx == N_NODES - 1) g_rowptr[N_NODES] = offp;
        }
    }
    (void)dummy;
}

__global__ void scatter_csr() {
    int e = blockIdx.x * blockDim.x + threadIdx.x;
    if (e >= N_EDGES) return;
    int d = g_dst[e];
    int pos = g_rowptr[d] + atomicAdd(&g_cur[d], 1);
    g_csrc[pos] = g_src[e];
}

// ---------------- fused 4-way GEMM: X[N,128] @ W[128,128] + b ----------------
template <bool RELU>
__global__ void __launch_bounds__(256, 2) gemm4(
    const float* __restrict__ Xin,
    const float* __restrict__ Wq, const float* __restrict__ bq,
    const float* __restrict__ Wk, const float* __restrict__ bk,
    const float* __restrict__ Wv, const float* __restrict__ bv,
    const float* __restrict__ Ws, const float* __restrict__ bs,
    float* __restrict__ skip_out)
{
    const float* X = Xin ? Xin : g_h;
    const float* W;
    const float* bias;
    float* Cout;
    switch (blockIdx.y) {
        case 0:  W = Wq; bias = bq; Cout = g_q; break;
        case 1:  W = Wk; bias = bk; Cout = g_k; break;
        case 2:  W = Wv; bias = bv; Cout = g_v; break;
        default: W = Ws; bias = bs; Cout = skip_out ? skip_out : g_h; break;
    }

    __shared__ float Xs[32][132];   // [k][m], padded
    __shared__ float Wsm[32][128];  // [k][n]

    const int tid = threadIdx.x;
    const int tx = tid & 15;
    const int ty = tid >> 4;
    const int m0 = blockIdx.x * 128;

    ull acc[8][4];
#pragma unroll
    for (int i = 0; i < 8; i++)
#pragma unroll
        for (int jj = 0; jj < 4; jj++) acc[i][jj] = 0ULL;

    for (int k0 = 0; k0 < 128; k0 += 32) {
#pragma unroll
        for (int it = 0; it < 4; it++) {
            int idx = it * 256 + tid;
            int row = idx >> 3;
            int f4  = idx & 7;
            int gr = m0 + row;
            float4 xv = make_float4(0.f, 0.f, 0.f, 0.f);
            if (gr < N_NODES) {
                xv = *reinterpret_cast<const float4*>(X + (size_t)gr * C + k0 + f4 * 4);
                if (RELU) {
                    xv.x = fmaxf(xv.x, 0.f); xv.y = fmaxf(xv.y, 0.f);
                    xv.z = fmaxf(xv.z, 0.f); xv.w = fmaxf(xv.w, 0.f);
                }
            }
            Xs[f4 * 4 + 0][row] = xv.x;
            Xs[f4 * 4 + 1][row] = xv.y;
            Xs[f4 * 4 + 2][row] = xv.z;
            Xs[f4 * 4 + 3][row] = xv.w;
        }
#pragma unroll
        for (int it = 0; it < 4; it++) {
            int idx = it * 256 + tid;
            int kk = idx >> 5;
            int f4 = idx & 31;
            float4 wv = *reinterpret_cast<const float4*>(W + (size_t)(k0 + kk) * C + f4 * 4);
            *reinterpret_cast<float4*>(&Wsm[kk][f4 * 4]) = wv;
        }
        __syncthreads();

#pragma unroll
        for (int kk = 0; kk < 32; kk++) {
            float4 a0 = *reinterpret_cast<float4*>(&Xs[kk][ty * 8]);
            float4 a1 = *reinterpret_cast<float4*>(&Xs[kk][ty * 8 + 4]);
            ulonglong2 wA = *reinterpret_cast<ulonglong2*>(&Wsm[kk][tx * 8]);
            ulonglong2 wB = *reinterpret_cast<ulonglong2*>(&Wsm[kk][tx * 8 + 4]);
            ull ad;
            ad = pack2(a0.x, a0.x);
            acc[0][0] = fma2(ad, wA.x, acc[0][0]); acc[0][1] = fma2(ad, wA.y, acc[0][1]);
            acc[0][2] = fma2(ad, wB.x, acc[0][2]); acc[0][3] = fma2(ad, wB.y, acc[0][3]);
            ad = pack2(a0.y, a0.y);
            acc[1][0] = fma2(ad, wA.x, acc[1][0]); acc[1][1] = fma2(ad, wA.y, acc[1][1]);
            acc[1][2] = fma2(ad, wB.x, acc[1][2]); acc[1][3] = fma2(ad, wB.y, acc[1][3]);
            ad = pack2(a0.z, a0.z);
            acc[2][0] = fma2(ad, wA.x, acc[2][0]); acc[2][1] = fma2(ad, wA.y, acc[2][1]);
            acc[2][2] = fma2(ad, wB.x, acc[2][2]); acc[2][3] = fma2(ad, wB.y, acc[2][3]);
            ad = pack2(a0.w, a0.w);
            acc[3][0] = fma2(ad, wA.x, acc[3][0]); acc[3][1] = fma2(ad, wA.y, acc[3][1]);
            acc[3][2] = fma2(ad, wB.x, acc[3][2]); acc[3][3] = fma2(ad, wB.y, acc[3][3]);
            ad = pack2(a1.x, a1.x);
            acc[4][0] = fma2(ad, wA.x, acc[4][0]); acc[4][1] = fma2(ad, wA.y, acc[4][1]);
            acc[4][2] = fma2(ad, wB.x, acc[4][2]); acc[4][3] = fma2(ad, wB.y, acc[4][3]);
            ad = pack2(a1.y, a1.y);
            acc[5][0] = fma2(ad, wA.x, acc[5][0]); acc[5][1] = fma2(ad, wA.y, acc[5][1]);
            acc[5][2] = fma2(ad, wB.x, acc[5][2]); acc[5][3] = fma2(ad, wB.y, acc[5][3]);
            ad = pack2(a1.z, a1.z);
            acc[6][0] = fma2(ad, wA.x, acc[6][0]); acc[6][1] = fma2(ad, wA.y, acc[6][1]);
            acc[6][2] = fma2(ad, wB.x, acc[6][2]); acc[6][3] = fma2(ad, wB.y, acc[6][3]);
            ad = pack2(a1.w, a1.w);
            acc[7][0] = fma2(ad, wA.x, acc[7][0]); acc[7][1] = fma2(ad, wA.y, acc[7][1]);
            acc[7][2] = fma2(ad, wB.x, acc[7][2]); acc[7][3] = fma2(ad, wB.y, acc[7][3]);
        }
        __syncthreads();
    }

    const int col = tx * 8;
    float bb[8];
#pragma unroll
    for (int j = 0; j < 8; j++) bb[j] = __ldg(bias + col + j);

#pragma unroll
    for (int i = 0; i < 8; i++) {
        int gr = m0 + ty * 8 + i;
        if (gr < N_NODES) {
            float o[8];
#pragma unroll
            for (int jj = 0; jj < 4; jj++) unpack2(acc[i][jj], o[2 * jj], o[2 * jj + 1]);
            float4 s0 = make_float4(o[0] + bb[0], o[1] + bb[1], o[2] + bb[2], o[3] + bb[3]);
            float4 s1 = make_float4(o[4] + bb[4], o[5] + bb[5], o[6] + bb[6], o[7] + bb[7]);
            *reinterpret_cast<float4*>(Cout + (size_t)gr * C + col)     = s0;
            *reinterpret_cast<float4*>(Cout + (size_t)gr * C + col + 4) = s1;
        }
    }
}

// ---------------- CSR attention: warp per destination node --------------------
// out must already hold the skip term for every row; this kernel adds the
// softmax-weighted aggregation in place (each row owned by exactly one warp).
__global__ void __launch_bounds__(256) csr_attn(float* __restrict__ outp) {
    float* out = outp ? outp : g_h;
    int d = blockIdx.x * 8 + (threadIdx.x >> 5);
    int lane = threadIdx.x & 31;
    __shared__ float sc_s[8][SCAP];
    if (d >= N_NODES) return;
    float* scw = sc_s[threadIdx.x >> 5];

    int r0 = g_rowptr[d];
    int deg = g_rowptr[d + 1] - r0;
    if (deg == 0) return;
    bool fast = (deg <= SCAP);

    float4 q4 = *reinterpret_cast<const float4*>(g_q + (size_t)d * C + lane * 4);

    // pass 1: scores + running max
    float m = -INFINITY;
    for (int i = 0; i < deg; i++) {
        int s = g_csrc[r0 + i];
        float4 k4 = *reinterpret_cast<const float4*>(g_k + (size_t)s * C + lane * 4);
        float t = q4.x * k4.x + q4.y * k4.y + q4.z * k4.z + q4.w * k4.w;
#pragma unroll
        for (int o = 16; o; o >>= 1) t += __shfl_xor_sync(0xffffffffu, t, o);
        t *= 0.0883883476483184405f;     // 1/sqrt(128)
        if (lane == 0) { if (fast) scw[i] = t; else g_sc[r0 + i] = t; }
        m = fmaxf(m, t);
    }
    if (!fast) __threadfence_block();
    __syncwarp();

    // pass 2: exp + sum (lane-parallel)
    float sum = 0.f;
    for (int i = lane; i < deg; i += 32) {
        float t = fast ? scw[i] : g_sc[r0 + i];
        float w = __expf(t - m);
        if (fast) scw[i] = w; else g_sc[r0 + i] = w;
        sum += w;
    }
#pragma unroll
    for (int o = 16; o; o >>= 1) sum += __shfl_xor_sync(0xffffffffu, sum, o);
    if (!fast) __threadfence_block();
    __syncwarp();
    float inv = 1.0f / sum;

    // pass 3: weighted accumulate
    float4 acc = make_float4(0.f, 0.f, 0.f, 0.f);
    for (int i = 0; i < deg; i++) {
        float alpha = (fast ? scw[i] : g_sc[r0 + i]) * inv;
        int s = g_csrc[r0 + i];
        float4 v4 = *reinterpret_cast<const float4*>(g_v + (size_t)s * C + lane * 4);
        acc.x += alpha * v4.x; acc.y += alpha * v4.y;
        acc.z += alpha * v4.z; acc.w += alpha * v4.w;
    }

    float* op = out + (size_t)d * C + lane * 4;
    float4 o4 = *reinterpret_cast<float4*>(op);
    o4.x += acc.x; o4.y += acc.y; o4.z += acc.z; o4.w += acc.w;
    *reinterpret_cast<float4*>(op) = o4;
}

// ---------------- launch ------------------------------------------------------
extern "C" void kernel_launch(void* const* d_in, const int* in_sizes, int n_in,
                              void* d_out, int out_size) {
    const float* x  = (const float*)d_in[0];
    const void*  ei = d_in[1];
    const float *Wq1 = (const float*)d_in[2],  *bq1 = (const float*)d_in[3];
    const float *Wk1 = (const float*)d_in[4],  *bk1 = (const float*)d_in[5];
    const float *Wv1 = (const float*)d_in[6],  *bv1 = (const float*)d_in[7];
    const float *Ws1 = (const float*)d_in[8],  *bs1 = (const float*)d_in[9];
    const float *Wq2 = (const float*)d_in[10], *bq2 = (const float*)d_in[11];
    const float *Wk2 = (const float*)d_in[12], *bk2 = (const float*)d_in[13];
    const float *Wv2 = (const float*)d_in[14], *bv2 = (const float*)d_in[15];
    const float *Ws2 = (const float*)d_in[16], *bs2 = (const float*)d_in[17];
    float* out = (float*)d_out;

    const dim3 ggrid((N_NODES + 127) / 128, 4);
    const int  nblk = (N_NODES + 255) / 256;
    const int  cblk = (2 * N_EDGES + 255) / 256;
    const int  eblk = (N_EDGES + 255) / 256;
    const int  ablk = (N_NODES + 7) / 8;

    // -------- CSR build (edges shared by both layers) --------
    detect_idx_dtype<<<1, 1>>>(ei);
    zero_counts<<<nblk, 256>>>();
    convert_hist<<<cblk, 256>>>(ei);
    scan_deg<<<1, 1024>>>();
    scatter_csr<<<eblk, 256>>>();

    // -------- layer 1 --------
    gemm4<false><<<ggrid, 256>>>(x, Wq1, bq1, Wk1, bk1, Wv1, bv1, Ws1, bs1, nullptr);
    csr_attn<<<ablk, 256>>>(nullptr);                 // g_h = skip + aggregation

    // -------- layer 2 (relu fused into GEMM load) --------
    gemm4<true><<<ggrid, 256>>>(nullptr, Wq2, bq2, Wk2, bk2, Wv2, bv2, Ws2, bs2, out);
    csr_attn<<<ablk, 256>>>(out);                     // d_out = skip + aggregation
}

// round 4
// speedup vs baseline: 1.5980x; 1.1194x over previous
#include <cuda_runtime.h>
#include <math.h>

#define N_NODES 100000
#define N_EDGES 800000
#define C 128
#define SCAN_B 98        // ceil(N_NODES / 1024)

// ---------------- scratch (static device globals; no allocation) -------------
__device__ float g_q[(size_t)N_NODES * C];
__device__ float g_k[(size_t)N_NODES * C];
__device__ float g_v[(size_t)N_NODES * C];
__device__ float g_h[(size_t)N_NODES * C];   // layer-1 output / layer-2 input
__device__ int   g_src[N_EDGES];
__device__ int   g_dst[N_EDGES];
__device__ int   g_deg[N_NODES];
__device__ int   g_cur[N_NODES];
__device__ int   g_rowptr[N_NODES + 1];
__device__ int   g_csrc[N_EDGES];            // src ids in CSR (dst-grouped) order
__device__ int   g_bsum[SCAN_B];
__device__ int   g_boff[SCAN_B];
__device__ int   g_is64;

// ---------------- packed f32x2 helpers (Blackwell) ---------------------------
typedef unsigned long long ull;

__device__ __forceinline__ ull pack2(float lo, float hi) {
    ull r;
    asm("mov.b64 %0, {%1, %2};" : "=l"(r) : "f"(lo), "f"(hi));
    return r;
}
__device__ __forceinline__ ull fma2(ull a, ull b, ull c) {
    ull d;
    asm("fma.rn.f32x2 %0, %1, %2, %3;" : "=l"(d) : "l"(a), "l"(b), "l"(c));
    return d;
}
__device__ __forceinline__ void unpack2(ull v, float& lo, float& hi) {
    asm("mov.b64 {%0, %1}, %2;" : "=f"(lo), "=f"(hi) : "l"(v));
}

// ---------------- CSR build ---------------------------------------------------
__global__ void detect_idx_dtype(const void* __restrict__ ei_raw) {
    // Deterministic: an int32 buffer read as int64 packs two random node ids
    // per word -> value >= 2^32 almost surely; 64 consecutive passes => int64.
    const long long* p = (const long long*)ei_raw;
    int lane = threadIdx.x;
    long long v0 = p[lane];
    long long v1 = p[lane + 32];
    bool bad = (v0 < 0) | (v0 >= N_NODES) | (v1 < 0) | (v1 >= N_NODES);
    unsigned b = __ballot_sync(0xffffffffu, bad);
    if (lane == 0) g_is64 = (b == 0u);
}

__global__ void zero_counts() {
    int i = blockIdx.x * blockDim.x + threadIdx.x;
    if (i < N_NODES) { g_deg[i] = 0; g_cur[i] = 0; }
}

__global__ void convert_hist(const void* __restrict__ ei_raw) {
    int i = blockIdx.x * blockDim.x + threadIdx.x;
    if (i >= 2 * N_EDGES) return;
    int v;
    if (g_is64) v = (int)((const long long*)ei_raw)[i];
    else        v = ((const int*)ei_raw)[i];
    if (i < N_EDGES) g_src[i] = v;
    else { g_dst[i - N_EDGES] = v; atomicAdd(&g_deg[v], 1); }
}

// three-kernel exclusive scan of g_deg -> g_rowptr
__global__ void __launch_bounds__(1024) scan_blk() {
    __shared__ int sh[1024];
    int b = blockIdx.x, tid = threadIdx.x;
    int idx = b * 1024 + tid;
    int v = (idx < N_NODES) ? g_deg[idx] : 0;
    sh[tid] = v;
    __syncthreads();
    for (int off = 1; off < 1024; off <<= 1) {
        int add = (tid >= off) ? sh[tid - off] : 0;
        __syncthreads();
        sh[tid] += add;
        __syncthreads();
    }
    if (idx < N_NODES) g_rowptr[idx] = sh[tid] - v;   // block-local exclusive
    if (tid == 1023) g_bsum[b] = sh[1023];
}

__global__ void __launch_bounds__(128) scan_top() {
    __shared__ int sh[128];
    int tid = threadIdx.x;
    int v = (tid < SCAN_B) ? g_bsum[tid] : 0;
    sh[tid] = v;
    __syncthreads();
    for (int off = 1; off < 128; off <<= 1) {
        int add = (tid >= off) ? sh[tid - off] : 0;
        __syncthreads();
        sh[tid] += add;
        __syncthreads();
    }
    if (tid < SCAN_B) g_boff[tid] = sh[tid] - v;
    if (tid == 0) g_rowptr[N_NODES] = N_EDGES;
}

__global__ void scan_add() {
    int idx = blockIdx.x * blockDim.x + threadIdx.x;
    if (idx < N_NODES) g_rowptr[idx] += g_boff[idx >> 10];
}

__global__ void scatter_csr() {
    int e = blockIdx.x * blockDim.x + threadIdx.x;
    if (e >= N_EDGES) return;
    int d = g_dst[e];
    int pos = g_rowptr[d] + atomicAdd(&g_cur[d], 1);
    g_csrc[pos] = g_src[e];
}

// ---------------- fused 4-way GEMM: X[N,128] @ W[128,128] + b ----------------
template <bool RELU>
__global__ void __launch_bounds__(256, 2) gemm4(
    const float* __restrict__ Xin,
    const float* __restrict__ Wq, const float* __restrict__ bq,
    const float* __restrict__ Wk, const float* __restrict__ bk,
    const float* __restrict__ Wv, const float* __restrict__ bv,
    const float* __restrict__ Ws, const float* __restrict__ bs,
    float* __restrict__ skip_out)
{
    const float* X = Xin ? Xin : g_h;
    const float* W;
    const float* bias;
    float* Cout;
    switch (blockIdx.y) {
        case 0:  W = Wq; bias = bq; Cout = g_q; break;
        case 1:  W = Wk; bias = bk; Cout = g_k; break;
        case 2:  W = Wv; bias = bv; Cout = g_v; break;
        default: W = Ws; bias = bs; Cout = skip_out ? skip_out : g_h; break;
    }

    __shared__ float Xs[32][132];   // [k][m], padded
    __shared__ float Wsm[32][128];  // [k][n]

    const int tid = threadIdx.x;
    const int tx = tid & 15;
    const int ty = tid >> 4;
    const int m0 = blockIdx.x * 128;

    ull acc[8][4];
#pragma unroll
    for (int i = 0; i < 8; i++)
#pragma unroll
        for (int jj = 0; jj < 4; jj++) acc[i][jj] = 0ULL;

    for (int k0 = 0; k0 < 128; k0 += 32) {
#pragma unroll
        for (int it = 0; it < 4; it++) {
            int idx = it * 256 + tid;
            int row = idx >> 3;
            int f4  = idx & 7;
            int gr = m0 + row;
            float4 xv = make_float4(0.f, 0.f, 0.f, 0.f);
            if (gr < N_NODES) {
                xv = *reinterpret_cast<const float4*>(X + (size_t)gr * C + k0 + f4 * 4);
                if (RELU) {
                    xv.x = fmaxf(xv.x, 0.f); xv.y = fmaxf(xv.y, 0.f);
                    xv.z = fmaxf(xv.z, 0.f); xv.w = fmaxf(xv.w, 0.f);
                }
            }
            Xs[f4 * 4 + 0][row] = xv.x;
            Xs[f4 * 4 + 1][row] = xv.y;
            Xs[f4 * 4 + 2][row] = xv.z;
            Xs[f4 * 4 + 3][row] = xv.w;
        }
#pragma unroll
        for (int it = 0; it < 4; it++) {
            int idx = it * 256 + tid;
            int kk = idx >> 5;
            int f4 = idx & 31;
            float4 wv = *reinterpret_cast<const float4*>(W + (size_t)(k0 + kk) * C + f4 * 4);
            *reinterpret_cast<float4*>(&Wsm[kk][f4 * 4]) = wv;
        }
        __syncthreads();

#pragma unroll
        for (int kk = 0; kk < 32; kk++) {
            float4 a0 = *reinterpret_cast<float4*>(&Xs[kk][ty * 8]);
            float4 a1 = *reinterpret_cast<float4*>(&Xs[kk][ty * 8 + 4]);
            ulonglong2 wA = *reinterpret_cast<ulonglong2*>(&Wsm[kk][tx * 8]);
            ulonglong2 wB = *reinterpret_cast<ulonglong2*>(&Wsm[kk][tx * 8 + 4]);
            ull ad;
            ad = pack2(a0.x, a0.x);
            acc[0][0] = fma2(ad, wA.x, acc[0][0]); acc[0][1] = fma2(ad, wA.y, acc[0][1]);
            acc[0][2] = fma2(ad, wB.x, acc[0][2]); acc[0][3] = fma2(ad, wB.y, acc[0][3]);
            ad = pack2(a0.y, a0.y);
            acc[1][0] = fma2(ad, wA.x, acc[1][0]); acc[1][1] = fma2(ad, wA.y, acc[1][1]);
            acc[1][2] = fma2(ad, wB.x, acc[1][2]); acc[1][3] = fma2(ad, wB.y, acc[1][3]);
            ad = pack2(a0.z, a0.z);
            acc[2][0] = fma2(ad, wA.x, acc[2][0]); acc[2][1] = fma2(ad, wA.y, acc[2][1]);
            acc[2][2] = fma2(ad, wB.x, acc[2][2]); acc[2][3] = fma2(ad, wB.y, acc[2][3]);
            ad = pack2(a0.w, a0.w);
            acc[3][0] = fma2(ad, wA.x, acc[3][0]); acc[3][1] = fma2(ad, wA.y, acc[3][1]);
            acc[3][2] = fma2(ad, wB.x, acc[3][2]); acc[3][3] = fma2(ad, wB.y, acc[3][3]);
            ad = pack2(a1.x, a1.x);
            acc[4][0] = fma2(ad, wA.x, acc[4][0]); acc[4][1] = fma2(ad, wA.y, acc[4][1]);
            acc[4][2] = fma2(ad, wB.x, acc[4][2]); acc[4][3] = fma2(ad, wB.y, acc[4][3]);
            ad = pack2(a1.y, a1.y);
            acc[5][0] = fma2(ad, wA.x, acc[5][0]); acc[5][1] = fma2(ad, wA.y, acc[5][1]);
            acc[5][2] = fma2(ad, wB.x, acc[5][2]); acc[5][3] = fma2(ad, wB.y, acc[5][3]);
            ad = pack2(a1.z, a1.z);
            acc[6][0] = fma2(ad, wA.x, acc[6][0]); acc[6][1] = fma2(ad, wA.y, acc[6][1]);
            acc[6][2] = fma2(ad, wB.x, acc[6][2]); acc[6][3] = fma2(ad, wB.y, acc[6][3]);
            ad = pack2(a1.w, a1.w);
            acc[7][0] = fma2(ad, wA.x, acc[7][0]); acc[7][1] = fma2(ad, wA.y, acc[7][1]);
            acc[7][2] = fma2(ad, wB.x, acc[7][2]); acc[7][3] = fma2(ad, wB.y, acc[7][3]);
        }
        __syncthreads();
    }

    const int col = tx * 8;
    float bb[8];
#pragma unroll
    for (int j = 0; j < 8; j++) bb[j] = __ldg(bias + col + j);

#pragma unroll
    for (int i = 0; i < 8; i++) {
        int gr = m0 + ty * 8 + i;
        if (gr < N_NODES) {
            float o[8];
#pragma unroll
            for (int jj = 0; jj < 4; jj++) unpack2(acc[i][jj], o[2 * jj], o[2 * jj + 1]);
            float4 s0 = make_float4(o[0] + bb[0], o[1] + bb[1], o[2] + bb[2], o[3] + bb[3]);
            float4 s1 = make_float4(o[4] + bb[4], o[5] + bb[5], o[6] + bb[6], o[7] + bb[7]);
            *reinterpret_cast<float4*>(Cout + (size_t)gr * C + col)     = s0;
            *reinterpret_cast<float4*>(Cout + (size_t)gr * C + col + 4) = s1;
        }
    }
}

// ---------------- CSR attention: warp per destination, online softmax ---------
// out must already hold the skip term for every row; adds softmax-weighted
// aggregation in place (each row owned by exactly one warp; no atomics).
__global__ void __launch_bounds__(256) csr_attn(float* __restrict__ outp) {
    float* out = outp ? outp : g_h;
    int d = blockIdx.x * 8 + (threadIdx.x >> 5);
    int lane = threadIdx.x & 31;
    if (d >= N_NODES) return;

    int r0 = g_rowptr[d];
    int deg = g_rowptr[d + 1] - r0;
    if (deg == 0) return;

    float4 q4 = *reinterpret_cast<const float4*>(g_q + (size_t)d * C + lane * 4);

    float m = -INFINITY, sum = 0.f;
    float4 acc = make_float4(0.f, 0.f, 0.f, 0.f);

    int s = g_csrc[r0];                      // software-prefetched source index
    for (int i = 0; i < deg; i++) {
        int s_next = (i + 1 < deg) ? g_csrc[r0 + i + 1] : 0;
        const float* kp = g_k + (size_t)s * C + lane * 4;
        const float* vp = g_v + (size_t)s * C + lane * 4;
        float4 k4 = *reinterpret_cast<const float4*>(kp);
        float4 v4 = *reinterpret_cast<const float4*>(vp);
        float t = q4.x * k4.x + q4.y * k4.y + q4.z * k4.z + q4.w * k4.w;
#pragma unroll
        for (int o = 16; o; o >>= 1) t += __shfl_xor_sync(0xffffffffu, t, o);
        t *= 0.0883883476483184405f;         // 1/sqrt(128)
        if (t > m) {                         // warp-uniform branch
            float corr = __expf(m - t);      // first iter: exp(-inf) = 0
            sum *= corr;
            acc.x *= corr; acc.y *= corr; acc.z *= corr; acc.w *= corr;
            m = t;
        }
        float w = __expf(t - m);
        sum += w;
        acc.x += w * v4.x; acc.y += w * v4.y;
        acc.z += w * v4.z; acc.w += w * v4.w;
        s = s_next;
    }

    float inv = 1.0f / sum;
    float* op = out + (size_t)d * C + lane * 4;
    float4 o4 = *reinterpret_cast<float4*>(op);
    o4.x += acc.x * inv; o4.y += acc.y * inv;
    o4.z += acc.z * inv; o4.w += acc.w * inv;
    *reinterpret_cast<float4*>(op) = o4;
}

// ---------------- launch ------------------------------------------------------
extern "C" void kernel_launch(void* const* d_in, const int* in_sizes, int n_in,
                              void* d_out, int out_size) {
    const float* x  = (const float*)d_in[0];
    const void*  ei = d_in[1];
    const float *Wq1 = (const float*)d_in[2],  *bq1 = (const float*)d_in[3];
    const float *Wk1 = (const float*)d_in[4],  *bk1 = (const float*)d_in[5];
    const float *Wv1 = (const float*)d_in[6],  *bv1 = (const float*)d_in[7];
    const float *Ws1 = (const float*)d_in[8],  *bs1 = (const float*)d_in[9];
    const float *Wq2 = (const float*)d_in[10], *bq2 = (const float*)d_in[11];
    const float *Wk2 = (const float*)d_in[12], *bk2 = (const float*)d_in[13];
    const float *Wv2 = (const float*)d_in[14], *bv2 = (const float*)d_in[15];
    const float *Ws2 = (const float*)d_in[16], *bs2 = (const float*)d_in[17];
    float* out = (float*)d_out;

    const dim3 ggrid((N_NODES + 127) / 128, 4);
    const int  nblk = (N_NODES + 255) / 256;
    const int  cblk = (2 * N_EDGES + 255) / 256;
    const int  eblk = (N_EDGES + 255) / 256;
    const int  ablk = (N_NODES + 7) / 8;

    // -------- CSR build (edges shared by both layers) --------
    detect_idx_dtype<<<1, 32>>>(ei);
    zero_counts<<<nblk, 256>>>();
    convert_hist<<<cblk, 256>>>(ei);
    scan_blk<<<SCAN_B, 1024>>>();
    scan_top<<<1, 128>>>();
    scan_add<<<nblk, 256>>>();
    scatter_csr<<<eblk, 256>>>();

    // -------- layer 1 --------
    gemm4<false><<<ggrid, 256>>>(x, Wq1, bq1, Wk1, bk1, Wv1, bv1, Ws1, bs1, nullptr);
    csr_attn<<<ablk, 256>>>(nullptr);                 // g_h = skip + aggregation

    // -------- layer 2 (relu fused into GEMM load) --------
    gemm4<true><<<ggrid, 256>>>(nullptr, Wq2, bq2, Wk2, bk2, Wv2, bv2, Ws2, bs2, out);
    csr_attn<<<ablk, 256>>>(out);                     // d_out = skip + aggregation
}

// round 6
// speedup vs baseline: 2.7778x; 1.7383x over previous
#include <cuda_runtime.h>
#include <math.h>
#include <stdint.h>

#define N_NODES 100000
#define N_EDGES 800000
#define C 128
#define SCAN_B 98        // ceil(N_NODES / 1024)

// ---------------- scratch (static device globals; no allocation) -------------
__device__ float g_q[(size_t)N_NODES * C];
__device__ float g_k[(size_t)N_NODES * C];
__device__ float g_v[(size_t)N_NODES * C];
__device__ float g_h[(size_t)N_NODES * C];   // layer-1 output / layer-2 input
__device__ float g_wt[2][4][C * C];          // transposed weights [n][k] per layer
__device__ int   g_src[N_EDGES];
__device__ int   g_dst[N_EDGES];
__device__ int   g_deg[N_NODES];
__device__ int   g_cur[N_NODES];
__device__ int   g_rowptr[N_NODES + 1];
__device__ int   g_csrc[N_EDGES];            // src ids in CSR (dst-grouped) order
__device__ int   g_bsum[SCAN_B];
__device__ int   g_boff[SCAN_B];
__device__ int   g_is64;

// ---------------- helpers ------------------------------------------------------
__device__ __forceinline__ uint32_t f2tf32(float v) {
    uint32_t t;
    asm("cvt.rna.tf32.f32 %0, %1;" : "=r"(t) : "f"(v));
    return t;
}

__device__ __forceinline__ void mma_tf32(float* c, const uint32_t* a, const uint32_t* b) {
    asm volatile(
        "mma.sync.aligned.m16n8k8.row.col.f32.tf32.tf32.f32 "
        "{%0,%1,%2,%3}, {%4,%5,%6,%7}, {%8,%9}, {%0,%1,%2,%3};"
        : "+f"(c[0]), "+f"(c[1]), "+f"(c[2]), "+f"(c[3])
        : "r"(a[0]), "r"(a[1]), "r"(a[2]), "r"(a[3]), "r"(b[0]), "r"(b[1]));
}

// ---------------- CSR build ----------------------------------------------------
__global__ void detect_idx_dtype(const void* __restrict__ ei_raw) {
    // Deterministic: an int32 buffer read as int64 packs two random node ids
    // per word -> value >= 2^32 almost surely; 64 consecutive passes => int64.
    const long long* p = (const long long*)ei_raw;
    int lane = threadIdx.x;
    long long v0 = p[lane];
    long long v1 = p[lane + 32];
    bool bad = (v0 < 0) | (v0 >= N_NODES) | (v1 < 0) | (v1 >= N_NODES);
    unsigned b = __ballot_sync(0xffffffffu, bad);
    if (lane == 0) g_is64 = (b == 0u);
}

__global__ void zero_counts() {
    int i = blockIdx.x * blockDim.x + threadIdx.x;
    if (i < N_NODES) { g_deg[i] = 0; g_cur[i] = 0; }
}

__global__ void convert_hist(const void* __restrict__ ei_raw) {
    int i = blockIdx.x * blockDim.x + threadIdx.x;
    if (i >= 2 * N_EDGES) return;
    int v;
    if (g_is64) v = (int)((const long long*)ei_raw)[i];
    else        v = ((const int*)ei_raw)[i];
    if (i < N_EDGES) g_src[i] = v;
    else { g_dst[i - N_EDGES] = v; atomicAdd(&g_deg[v], 1); }
}

__global__ void __launch_bounds__(1024) scan_blk() {
    __shared__ int sh[1024];
    int b = blockIdx.x, tid = threadIdx.x;
    int idx = b * 1024 + tid;
    int v = (idx < N_NODES) ? g_deg[idx] : 0;
    sh[tid] = v;
    __syncthreads();
    for (int off = 1; off < 1024; off <<= 1) {
        int add = (tid >= off) ? sh[tid - off] : 0;
        __syncthreads();
        sh[tid] += add;
        __syncthreads();
    }
    if (idx < N_NODES) g_rowptr[idx] = sh[tid] - v;
    if (tid == 1023) g_bsum[b] = sh[1023];
}

__global__ void __launch_bounds__(128) scan_top() {
    __shared__ int sh[128];
    int tid = threadIdx.x;
    int v = (tid < SCAN_B) ? g_bsum[tid] : 0;
    sh[tid] = v;
    __syncthreads();
    for (int off = 1; off < 128; off <<= 1) {
        int add = (tid >= off) ? sh[tid - off] : 0;
        __syncthreads();
        sh[tid] += add;
        __syncthreads();
    }
    if (tid < SCAN_B) g_boff[tid] = sh[tid] - v;
    if (tid == 0) g_rowptr[N_NODES] = N_EDGES;
}

__global__ void scan_add() {
    int idx = blockIdx.x * blockDim.x + threadIdx.x;
    if (idx < N_NODES) g_rowptr[idx] += g_boff[idx >> 10];
}

__global__ void scatter_csr() {
    int e = blockIdx.x * blockDim.x + threadIdx.x;
    if (e >= N_EDGES) return;
    int d = g_dst[e];
    int pos = g_rowptr[d] + atomicAdd(&g_cur[d], 1);
    g_csrc[pos] = g_src[e];
}

// ---------------- weight transpose: g_wt[layer][y][n*128+k] = W[k*128+n] ------
__global__ void transpose_w(const float* __restrict__ W0, const float* __restrict__ W1,
                            const float* __restrict__ W2, const float* __restrict__ W3,
                            int layer) {
    const float* W = (blockIdx.y == 0) ? W0 : (blockIdx.y == 1) ? W1
                   : (blockIdx.y == 2) ? W2 : W3;
    float* outp = &g_wt[layer][blockIdx.y][0];
    int i = blockIdx.x * 256 + threadIdx.x;     // 0..16383
    int k = i >> 7, n = i & 127;
    outp[n * C + k] = W[i];                     // coalesced read, scattered write
}

// ---------------- tf32 mma.sync GEMM: X[128,128] @ W[128,128] + b -------------
// grid = (782, 4); blockIdx.y selects q/k/v/skip. Dynamic smem (70 KB):
//   As[128][68] floats (X tile, tf32-rounded)  |  Bs[128][68] ([n][k] W tile) | bias[128]
#define AROW 68
#define AS_OFF 0
#define BS_OFF (128 * AROW)
#define BIAS_OFF (2 * 128 * AROW)
#define SMEM_SZ ((2 * 128 * AROW + 128) * 4)

template <bool RELU>
__global__ void __launch_bounds__(256, 2) gemm_mma(
    const float* __restrict__ Xin,
    const float* __restrict__ b0, const float* __restrict__ b1,
    const float* __restrict__ b2, const float* __restrict__ b3,
    int layer, float* __restrict__ skip_out)
{
    extern __shared__ float sm[];
    float* As = sm + AS_OFF;
    float* Bs = sm + BS_OFF;
    float* bias_s = sm + BIAS_OFF;

    const int tid = threadIdx.x, wid = tid >> 5, lane = tid & 31;
    const int y = blockIdx.y;
    const int m0 = blockIdx.x * 128;

    const float* X = Xin ? Xin : g_h;
    const float* Wt = &g_wt[layer][y][0];
    const float* bias;
    float* Cout;
    switch (y) {
        case 0:  bias = b0; Cout = g_q; break;
        case 1:  bias = b1; Cout = g_k; break;
        case 2:  bias = b2; Cout = g_v; break;
        default: bias = b3; Cout = skip_out ? skip_out : g_h; break;
    }

    if (tid < 128) bias_s[tid] = bias[tid];

    const int rw = (wid & 3) * 32;     // warp row offset (0,32,64,96)
    const int cw = (wid >> 2) * 64;    // warp col offset (0,64)

    float acc[2][8][4];
#pragma unroll
    for (int mb = 0; mb < 2; mb++)
#pragma unroll
        for (int t = 0; t < 8; t++)
#pragma unroll
            for (int j = 0; j < 4; j++) acc[mb][t][j] = 0.f;

    const uint32_t* ap = reinterpret_cast<const uint32_t*>(
        As + (rw + (lane >> 2)) * AROW + (lane & 3));
    const uint32_t* bp = reinterpret_cast<const uint32_t*>(
        Bs + (cw + (lane >> 2)) * AROW + (lane & 3));

    for (int ch = 0; ch < 2; ch++) {           // K chunks of 64
        const int kc = ch * 64;
        __syncthreads();                       // previous chunk's frags consumed
        // fill As: X rows (tf32-rounded), optional ReLU
#pragma unroll
        for (int i = 0; i < 8; i++) {
            int idx = i * 256 + tid;           // 0..2047 float4 slots
            int row = idx >> 4, f4 = idx & 15;
            int gr = m0 + row;
            float4 xv = make_float4(0.f, 0.f, 0.f, 0.f);
            if (gr < N_NODES)
                xv = *reinterpret_cast<const float4*>(X + (size_t)gr * C + kc + f4 * 4);
            if (RELU) {
                xv.x = fmaxf(xv.x, 0.f); xv.y = fmaxf(xv.y, 0.f);
                xv.z = fmaxf(xv.z, 0.f); xv.w = fmaxf(xv.w, 0.f);
            }
            uint4 tv = make_uint4(f2tf32(xv.x), f2tf32(xv.y), f2tf32(xv.z), f2tf32(xv.w));
            *reinterpret_cast<uint4*>(As + row * AROW + f4 * 4) = tv;
        }
        // fill Bs: Wt[n][k] (tf32-rounded)
#pragma unroll
        for (int i = 0; i < 8; i++) {
            int idx = i * 256 + tid;
            int n = idx >> 4, f4 = idx & 15;
            float4 wv = *reinterpret_cast<const float4*>(Wt + (size_t)n * C + kc + f4 * 4);
            uint4 tv = make_uint4(f2tf32(wv.x), f2tf32(wv.y), f2tf32(wv.z), f2tf32(wv.w));
            *reinterpret_cast<uint4*>(Bs + n * AROW + f4 * 4) = tv;
        }
        __syncthreads();

#pragma unroll
        for (int ks = 0; ks < 8; ks++) {
            const int kk = ks * 8;
            uint32_t a[2][4];
#pragma unroll
            for (int mb = 0; mb < 2; mb++) {
                const uint32_t* am = ap + mb * 16 * AROW + kk;
                a[mb][0] = am[0];
                a[mb][1] = am[8 * AROW];
                a[mb][2] = am[4];
                a[mb][3] = am[8 * AROW + 4];
            }
            uint32_t b[8][2];
#pragma unroll
            for (int t = 0; t < 8; t++) {
                const uint32_t* bm = bp + t * 8 * AROW + kk;
                b[t][0] = bm[0];
                b[t][1] = bm[4];
            }
#pragma unroll
            for (int mb = 0; mb < 2; mb++)
#pragma unroll
                for (int t = 0; t < 8; t++)
                    mma_tf32(acc[mb][t], a[mb], b[t]);
        }
    }

    // epilogue: direct register stores; each (row, tile) pair is a 8B store,
    // 4 lanes/row cover a contiguous 32B sector.
#pragma unroll
    for (int mb = 0; mb < 2; mb++) {
        int r1 = m0 + rw + mb * 16 + (lane >> 2);
        int r2 = r1 + 8;
#pragma unroll
        for (int t = 0; t < 8; t++) {
            int n0 = cw + t * 8 + (lane & 3) * 2;
            float bb0 = bias_s[n0], bb1 = bias_s[n0 + 1];
            if (r1 < N_NODES) {
                float2 s = make_float2(acc[mb][t][0] + bb0, acc[mb][t][1] + bb1);
                *reinterpret_cast<float2*>(Cout + (size_t)r1 * C + n0) = s;
            }
            if (r2 < N_NODES) {
                float2 s = make_float2(acc[mb][t][2] + bb0, acc[mb][t][3] + bb1);
                *reinterpret_cast<float2*>(Cout + (size_t)r2 * C + n0) = s;
            }
        }
    }
}

// ---------------- CSR attention: warp per destination, online softmax ---------
__global__ void __launch_bounds__(256) csr_attn(float* __restrict__ outp) {
    float* out = outp ? outp : g_h;
    int d = blockIdx.x * 8 + (threadIdx.x >> 5);
    int lane = threadIdx.x & 31;
    if (d >= N_NODES) return;

    int r0 = g_rowptr[d];
    int deg = g_rowptr[d + 1] - r0;
    if (deg == 0) return;

    float4 q4 = *reinterpret_cast<const float4*>(g_q + (size_t)d * C + lane * 4);

    float m = -INFINITY, sum = 0.f;
    float4 acc = make_float4(0.f, 0.f, 0.f, 0.f);

    int s = g_csrc[r0];
    for (int i = 0; i < deg; i++) {
        int s_next = (i + 1 < deg) ? g_csrc[r0 + i + 1] : 0;
        float4 k4 = *reinterpret_cast<const float4*>(g_k + (size_t)s * C + lane * 4);
        float4 v4 = *reinterpret_cast<const float4*>(g_v + (size_t)s * C + lane * 4);
        float t = q4.x * k4.x + q4.y * k4.y + q4.z * k4.z + q4.w * k4.w;
#pragma unroll
        for (int o = 16; o; o >>= 1) t += __shfl_xor_sync(0xffffffffu, t, o);
        t *= 0.0883883476483184405f;         // 1/sqrt(128)
        if (t > m) {                         // warp-uniform branch
            float corr = __expf(m - t);      // first iter: exp(-inf) = 0
            sum *= corr;
            acc.x *= corr; acc.y *= corr; acc.z *= corr; acc.w *= corr;
            m = t;
        }
        float w = __expf(t - m);
        sum += w;
        acc.x += w * v4.x; acc.y += w * v4.y;
        acc.z += w * v4.z; acc.w += w * v4.w;
        s = s_next;
    }

    float inv = 1.0f / sum;
    float* op = out + (size_t)d * C + lane * 4;
    float4 o4 = *reinterpret_cast<float4*>(op);
    o4.x += acc.x * inv; o4.y += acc.y * inv;
    o4.z += acc.z * inv; o4.w += acc.w * inv;
    *reinterpret_cast<float4*>(op) = o4;
}

// ---------------- launch ------------------------------------------------------
extern "C" void kernel_launch(void* const* d_in, const int* in_sizes, int n_in,
                              void* d_out, int out_size) {
    const float* x  = (const float*)d_in[0];
    const void*  ei = d_in[1];
    const float *Wq1 = (const float*)d_in[2],  *bq1 = (const float*)d_in[3];
    const float *Wk1 = (const float*)d_in[4],  *bk1 = (const float*)d_in[5];
    const float *Wv1 = (const float*)d_in[6],  *bv1 = (const float*)d_in[7];
    const float *Ws1 = (const float*)d_in[8],  *bs1 = (const float*)d_in[9];
    const float *Wq2 = (const float*)d_in[10], *bq2 = (const float*)d_in[11];
    const float *Wk2 = (const float*)d_in[12], *bk2 = (const float*)d_in[13];
    const float *Wv2 = (const float*)d_in[14], *bv2 = (const float*)d_in[15];
    const float *Ws2 = (const float*)d_in[16], *bs2 = (const float*)d_in[17];
    float* out = (float*)d_out;

    // Opt-in to >48KB dynamic smem (idempotent attribute set; not a stream op)
    cudaFuncSetAttribute(gemm_mma<false>, cudaFuncAttributeMaxDynamicSharedMemorySize, SMEM_SZ);
    cudaFuncSetAttribute(gemm_mma<true>,  cudaFuncAttributeMaxDynamicSharedMemorySize, SMEM_SZ);

    const dim3 ggrid((N_NODES + 127) / 128, 4);
    const int  nblk = (N_NODES + 255) / 256;
    const int  cblk = (2 * N_EDGES + 255) / 256;
    const int  eblk = (N_EDGES + 255) / 256;
    const int  ablk = (N_NODES + 7) / 8;

    // -------- CSR build + weight transposes --------
    detect_idx_dtype<<<1, 32>>>(ei);
    zero_counts<<<nblk, 256>>>();
    convert_hist<<<cblk, 256>>>(ei);
    scan_blk<<<SCAN_B, 1024>>>();
    scan_top<<<1, 128>>>();
    scan_add<<<nblk, 256>>>();
    scatter_csr<<<eblk, 256>>>();
    transpose_w<<<dim3(64, 4), 256>>>(Wq1, Wk1, Wv1, Ws1, 0);
    transpose_w<<<dim3(64, 4), 256>>>(Wq2, Wk2, Wv2, Ws2, 1);

    // -------- layer 1 --------
    gemm_mma<false><<<ggrid, 256, SMEM_SZ>>>(x, bq1, bk1, bv1, bs1, 0, nullptr);
    csr_attn<<<ablk, 256>>>(nullptr);                 // g_h = skip + aggregation

    // -------- layer 2 (relu fused into GEMM load) --------
    gemm_mma<true><<<ggrid, 256, SMEM_SZ>>>(nullptr, bq2, bk2, bv2, bs2, 1, out);
    csr_attn<<<ablk, 256>>>(out);                     // d_out = skip + aggregation
}